// round 1
// baseline (speedup 1.0000x reference)
#include <cuda_runtime.h>
#include <cuda_bf16.h>

// ---------------------------------------------------------------------------
// Problem constants
// ---------------------------------------------------------------------------
// B=64, H=W=56, C=256, NH=8, WS=7, SS=3, HID=1024, N=49
// windowed rows: 64 * 64 * 49 = 200704
#define ROWS_TOT 200704

// ---------------------------------------------------------------------------
// Scratch (device globals — no allocation allowed)
// ---------------------------------------------------------------------------
__device__ __nv_bfloat16 g_hwin[(size_t)ROWS_TOT * 256];   // LN1+shift+partition out
__device__ __nv_bfloat16 g_qkv [(size_t)ROWS_TOT * 768];   // qkv GEMM out
__device__ __nv_bfloat16 g_attn[(size_t)ROWS_TOT * 256];   // attention out (windowed rows)
__device__ float         g_x1  [(size_t)ROWS_TOT * 256];   // x + proj(attn) (natural rows)
__device__ __nv_bfloat16 g_h2  [(size_t)ROWS_TOT * 256];   // LN2 out
__device__ __nv_bfloat16 g_hid [(size_t)ROWS_TOT * 1024];  // gelu(fc1) out
__device__ __nv_bfloat16 g_wq[768 * 256];
__device__ __nv_bfloat16 g_wp[256 * 256];
__device__ __nv_bfloat16 g_w1[1024 * 256];
__device__ __nv_bfloat16 g_w2[256 * 1024];

// ---------------------------------------------------------------------------
// Windowed row <-> x row mapping.
// windowed row m = (((b*8+wi)*8+wj)*7+i)*7+j  maps to x row
// b*3136 + ((wi*7+i+3)%56)*56 + ((wj*7+j+3)%56)   (roll by -3 then partition,
// and its exact inverse for window-reverse + roll +3)
// ---------------------------------------------------------------------------
__device__ __forceinline__ int win2x(int m) {
    int b   = m / 3136;
    int r   = m - b * 3136;
    int w64 = r / 49;
    int tok = r - w64 * 49;
    int wi = w64 >> 3, wj = w64 & 7;
    int i = tok / 7, j = tok - (tok / 7) * 7;
    int hh = wi * 7 + i + 3; hh = (hh >= 56) ? hh - 56 : hh;
    int ww = wj * 7 + j + 3; ww = (ww >= 56) ? ww - 56 : ww;
    return b * 3136 + hh * 56 + ww;
}

// ---------------------------------------------------------------------------
// fp32 -> bf16 weight conversion
// ---------------------------------------------------------------------------
__global__ void cvt_kernel(const float* __restrict__ src, __nv_bfloat16* __restrict__ dst, int n) {
    int i = blockIdx.x * blockDim.x + threadIdx.x;
    if (i < n) dst[i] = __float2bfloat16(src[i]);
}

// ---------------------------------------------------------------------------
// LayerNorm (one warp per row of 256). REMAP: read x at shifted/partitioned row.
// ---------------------------------------------------------------------------
template <bool REMAP>
__global__ __launch_bounds__(256) void ln_kernel(
    const float* __restrict__ X, const float* __restrict__ gw,
    const float* __restrict__ gb, __nv_bfloat16* __restrict__ out)
{
    int row  = blockIdx.x * 8 + (threadIdx.x >> 5);
    int lane = threadIdx.x & 31;
    int src  = REMAP ? win2x(row) : row;
    const float4* xr = (const float4*)(X + (size_t)src * 256) + lane * 2;
    float4 u0 = xr[0], u1 = xr[1];
    float s  = u0.x + u0.y + u0.z + u0.w + u1.x + u1.y + u1.z + u1.w;
    float s2 = u0.x*u0.x + u0.y*u0.y + u0.z*u0.z + u0.w*u0.w
             + u1.x*u1.x + u1.y*u1.y + u1.z*u1.z + u1.w*u1.w;
#pragma unroll
    for (int o = 16; o > 0; o >>= 1) {
        s  += __shfl_xor_sync(0xffffffffu, s, o);
        s2 += __shfl_xor_sync(0xffffffffu, s2, o);
    }
    float mean = s * (1.f / 256.f);
    float var  = s2 * (1.f / 256.f) - mean * mean;
    float inv  = rsqrtf(var + 1e-5f);
    const float4* wr = (const float4*)gw + lane * 2;
    const float4* br = (const float4*)gb + lane * 2;
    float4 w0 = wr[0], w1 = wr[1], b0 = br[0], b1 = br[1];
    __nv_bfloat162 o2[4];
    o2[0].x = __float2bfloat16((u0.x - mean) * inv * w0.x + b0.x);
    o2[0].y = __float2bfloat16((u0.y - mean) * inv * w0.y + b0.y);
    o2[1].x = __float2bfloat16((u0.z - mean) * inv * w0.z + b0.z);
    o2[1].y = __float2bfloat16((u0.w - mean) * inv * w0.w + b0.w);
    o2[2].x = __float2bfloat16((u1.x - mean) * inv * w1.x + b1.x);
    o2[2].y = __float2bfloat16((u1.y - mean) * inv * w1.y + b1.y);
    o2[3].x = __float2bfloat16((u1.z - mean) * inv * w1.z + b1.z);
    o2[3].y = __float2bfloat16((u1.w - mean) * inv * w1.w + b1.w);
    *(uint4*)(out + (size_t)row * 256 + lane * 8) = *(uint4*)o2;
}

// ---------------------------------------------------------------------------
// bf16 mma.sync GEMM: C[M,N] = A[M,K] * W[N,K]^T + bias, with epilogues:
//   EPI 0: bf16 out                         (QKV)
//   EPI 1: fp32 out = Res[map(r)] + acc     (proj + window-reverse + residual)
//   EPI 2: bf16 out = gelu(acc)             (FC1)
//   EPI 3: fp32 out = Res[r] + acc          (FC2 -> d_out)
// Tiles: BM=128, BN=128, BK=32, 256 threads (8 warps, 2x4), warp 64x32.
// ---------------------------------------------------------------------------
__device__ __forceinline__ void mma_bf16(float c[4], const unsigned a[4], const unsigned b[2]) {
    asm volatile(
        "mma.sync.aligned.m16n8k16.row.col.f32.bf16.bf16.f32 "
        "{%0,%1,%2,%3}, {%4,%5,%6,%7}, {%8,%9}, {%0,%1,%2,%3};\n"
        : "+f"(c[0]), "+f"(c[1]), "+f"(c[2]), "+f"(c[3])
        : "r"(a[0]), "r"(a[1]), "r"(a[2]), "r"(a[3]), "r"(b[0]), "r"(b[1]));
}

__device__ __forceinline__ float gelu_exact(float v) {
    return 0.5f * v * (1.f + erff(v * 0.70710678118654752f));
}

template <int EPI>
__global__ __launch_bounds__(256) void gemm_kernel(
    const __nv_bfloat16* __restrict__ A, const __nv_bfloat16* __restrict__ Bw,
    const float* __restrict__ bias, void* __restrict__ Out,
    const float* __restrict__ Res, int M, int N, int K)
{
    constexpr int SK = 40;  // padded k-stride (bf16) -> conflict-free frag LDS
    __shared__ __nv_bfloat16 As[128 * SK];
    __shared__ __nv_bfloat16 Bs[128 * SK];
    const int tid = threadIdx.x;
    const int m0 = blockIdx.x * 128, n0 = blockIdx.y * 128;
    const int lane = tid & 31, warp = tid >> 5;
    const int wm = (warp & 1) * 64, wn = (warp >> 1) * 32;
    const int gr = lane >> 2, kc = (lane & 3) * 2;
    const int vr = tid >> 2, vc = (tid & 3) * 8;

    float acc[4][4][4];
#pragma unroll
    for (int a = 0; a < 4; a++)
#pragma unroll
        for (int b = 0; b < 4; b++)
#pragma unroll
            for (int c = 0; c < 4; c++) acc[a][b][c] = 0.f;

    const __nv_bfloat16* Ag = A  + (size_t)m0 * K;
    const __nv_bfloat16* Bg = Bw + (size_t)n0 * K;
    uint4 pa0 = *(const uint4*)(Ag + (size_t)vr * K + vc);
    uint4 pa1 = *(const uint4*)(Ag + (size_t)(vr + 64) * K + vc);
    uint4 pb0 = *(const uint4*)(Bg + (size_t)vr * K + vc);
    uint4 pb1 = *(const uint4*)(Bg + (size_t)(vr + 64) * K + vc);

    for (int ko = 0; ko < K; ko += 32) {
        *(uint4*)&As[vr * SK + vc]        = pa0;
        *(uint4*)&As[(vr + 64) * SK + vc] = pa1;
        *(uint4*)&Bs[vr * SK + vc]        = pb0;
        *(uint4*)&Bs[(vr + 64) * SK + vc] = pb1;
        __syncthreads();
        if (ko + 32 < K) {  // prefetch next tile into registers
            int k2 = ko + 32;
            pa0 = *(const uint4*)(Ag + (size_t)vr * K + k2 + vc);
            pa1 = *(const uint4*)(Ag + (size_t)(vr + 64) * K + k2 + vc);
            pb0 = *(const uint4*)(Bg + (size_t)vr * K + k2 + vc);
            pb1 = *(const uint4*)(Bg + (size_t)(vr + 64) * K + k2 + vc);
        }
#pragma unroll
        for (int kk = 0; kk < 32; kk += 16) {
            unsigned af[4][4], bfr[4][2];
#pragma unroll
            for (int mt = 0; mt < 4; mt++) {
                const __nv_bfloat16* p = &As[(wm + mt * 16 + gr) * SK + kk + kc];
                af[mt][0] = *(const unsigned*)p;
                af[mt][1] = *(const unsigned*)(p + 8 * SK);
                af[mt][2] = *(const unsigned*)(p + 8);
                af[mt][3] = *(const unsigned*)(p + 8 * SK + 8);
            }
#pragma unroll
            for (int nt = 0; nt < 4; nt++) {
                const __nv_bfloat16* p = &Bs[(wn + nt * 8 + gr) * SK + kk + kc];
                bfr[nt][0] = *(const unsigned*)p;
                bfr[nt][1] = *(const unsigned*)(p + 8);
            }
#pragma unroll
            for (int mt = 0; mt < 4; mt++)
#pragma unroll
                for (int nt = 0; nt < 4; nt++)
                    mma_bf16(acc[mt][nt], af[mt], bfr[nt]);
        }
        __syncthreads();
    }

    // epilogue: c0,c1 -> (row, col..col+1); c2,c3 -> (row+8, ...)
#pragma unroll
    for (int mt = 0; mt < 4; mt++) {
#pragma unroll
        for (int hh = 0; hh < 2; hh++) {
            int r = m0 + wm + mt * 16 + gr + hh * 8;
            int orow = (EPI == 1) ? win2x(r) : r;
#pragma unroll
            for (int nt = 0; nt < 4; nt++) {
                int col = n0 + wn + nt * 8 + kc;
                float2 bb = *(const float2*)&bias[col];
                float v0 = acc[mt][nt][hh * 2 + 0] + bb.x;
                float v1 = acc[mt][nt][hh * 2 + 1] + bb.y;
                if (EPI == 0) {
                    __nv_bfloat162 o; o.x = __float2bfloat16(v0); o.y = __float2bfloat16(v1);
                    *(__nv_bfloat162*)((__nv_bfloat16*)Out + (size_t)r * N + col) = o;
                } else if (EPI == 2) {
                    __nv_bfloat162 o;
                    o.x = __float2bfloat16(gelu_exact(v0));
                    o.y = __float2bfloat16(gelu_exact(v1));
                    *(__nv_bfloat162*)((__nv_bfloat16*)Out + (size_t)r * N + col) = o;
                } else {
                    float2 rr = *(const float2*)&Res[(size_t)orow * N + col];
                    float2 o; o.x = rr.x + v0; o.y = rr.y + v1;
                    *(float2*)((float*)Out + (size_t)orow * N + col) = o;
                }
            }
        }
    }
}

// ---------------------------------------------------------------------------
// Attention: one CTA per (window, head). N=49 tokens, hd=32.
// logits = (q/sqrt(32))·k + rel_pos_bias + shift_mask; softmax; out = S·V.
// Threads: pairs (n, half) for n<49; K/V staged fp32 in smem; Q in registers.
// ---------------------------------------------------------------------------
__global__ __launch_bounds__(128) void attn_kernel(
    const __nv_bfloat16* __restrict__ qkv, const float* __restrict__ rpb,
    __nv_bfloat16* __restrict__ outp)
{
    __shared__ float ks[49 * 32];
    __shared__ float vs[49 * 32];
    __shared__ float sm[49 * 50];
    __shared__ int gids[49];
    const int win = blockIdx.x, head = blockIdx.y;
    const int tid = threadIdx.x;
    const size_t qkvbase = (size_t)win * 49 * 768 + head * 32;

    for (int idx = tid; idx < 49 * 16; idx += 128) {
        int n = idx >> 4, d2 = (idx & 15) * 2;
        const __nv_bfloat16* p = qkv + qkvbase + (size_t)n * 768 + d2;
        __nv_bfloat162 k2 = *(const __nv_bfloat162*)(p + 256);
        __nv_bfloat162 v2 = *(const __nv_bfloat162*)(p + 512);
        ks[n * 32 + d2]     = __bfloat162float(k2.x);
        ks[n * 32 + d2 + 1] = __bfloat162float(k2.y);
        vs[n * 32 + d2]     = __bfloat162float(v2.x);
        vs[n * 32 + d2 + 1] = __bfloat162float(v2.y);
    }
    if (tid < 49) {
        int w64 = win & 63;
        int hh = (w64 >> 3) * 7 + tid / 7;
        int ww = (w64 & 7) * 7 + tid % 7;
        int gh = hh < 49 ? 0 : (hh < 53 ? 1 : 2);
        int gw = ww < 49 ? 0 : (ww < 53 ? 1 : 2);
        gids[tid] = gh * 3 + gw;
    }
    __syncthreads();

    const int n = tid >> 1, half = tid & 1;
    if (n < 49) {
        float qreg[32];
        const __nv_bfloat16* qp = qkv + qkvbase + (size_t)n * 768;
#pragma unroll
        for (int d2 = 0; d2 < 16; d2++) {
            __nv_bfloat162 q2 = *(const __nv_bfloat162*)(qp + d2 * 2);
            qreg[d2 * 2]     = __bfloat162float(q2.x) * 0.17677669529663687f;
            qreg[d2 * 2 + 1] = __bfloat162float(q2.y) * 0.17677669529663687f;
        }
        int gn = gids[n];
        int in_ = n / 7, jn = n - in_ * 7;
        for (int mi = 0; mi < 25; mi++) {
            int m = mi * 2 + half;
            if (m > 48) break;
            float acc = 0.f;
#pragma unroll
            for (int d = 0; d < 32; d++) acc += qreg[d] * ks[m * 32 + d];
            int im = m / 7, jm = m - im * 7;
            float bv  = __ldg(&rpb[((in_ - im + 6) * 13 + (jn - jm + 6)) * 8 + head]);
            float msk = (gids[m] != gn) ? -100.f : 0.f;
            sm[n * 50 + m] = acc + bv + msk;
        }
    }
    __syncwarp();
    // softmax: the two paired threads (adjacent lanes) cooperate
    float mx = -1e30f;
    if (n < 49)
        for (int m = half; m < 49; m += 2) mx = fmaxf(mx, sm[n * 50 + m]);
    mx = fmaxf(mx, __shfl_xor_sync(0xffffffffu, mx, 1));
    float ssum = 0.f;
    if (n < 49)
        for (int m = half; m < 49; m += 2) {
            float e = __expf(sm[n * 50 + m] - mx);
            sm[n * 50 + m] = e;
            ssum += e;
        }
    ssum += __shfl_xor_sync(0xffffffffu, ssum, 1);
    __syncthreads();

    if (n < 49) {
        float invs = 1.f / ssum;
        const int d0 = half * 16;
        float acc[16];
#pragma unroll
        for (int d = 0; d < 16; d++) acc[d] = 0.f;
        for (int m = 0; m < 49; m++) {
            float s = sm[n * 50 + m];
            const float* vrow = &vs[m * 32 + d0];
#pragma unroll
            for (int d = 0; d < 16; d++) acc[d] += s * vrow[d];
        }
        size_t ob = (size_t)(win * 49 + n) * 256 + head * 32 + d0;
        __nv_bfloat162 o2[8];
#pragma unroll
        for (int d2 = 0; d2 < 8; d2++) {
            o2[d2].x = __float2bfloat16(acc[d2 * 2] * invs);
            o2[d2].y = __float2bfloat16(acc[d2 * 2 + 1] * invs);
        }
        *(uint4*)(outp + ob)     = *(uint4*)&o2[0];
        *(uint4*)(outp + ob + 8) = *(uint4*)&o2[4];
    }
}

// ---------------------------------------------------------------------------
// Launch
// ---------------------------------------------------------------------------
extern "C" void kernel_launch(void* const* d_in, const int* in_sizes, int n_in,
                              void* d_out, int out_size)
{
    const float* x     = (const float*)d_in[0];
    const float* n1w   = (const float*)d_in[1];
    const float* n1b   = (const float*)d_in[2];
    const float* qkvw  = (const float*)d_in[3];
    const float* qkvb  = (const float*)d_in[4];
    const float* rpb   = (const float*)d_in[5];
    const float* projw = (const float*)d_in[6];
    const float* projb = (const float*)d_in[7];
    const float* n2w   = (const float*)d_in[8];
    const float* n2b   = (const float*)d_in[9];
    const float* fc1w  = (const float*)d_in[10];
    const float* fc1b  = (const float*)d_in[11];
    const float* fc2w  = (const float*)d_in[12];
    const float* fc2b  = (const float*)d_in[13];

    void *p_hwin, *p_qkv, *p_attn, *p_x1, *p_h2, *p_hid, *p_wq, *p_wp, *p_w1, *p_w2;
    cudaGetSymbolAddress(&p_hwin, g_hwin);
    cudaGetSymbolAddress(&p_qkv,  g_qkv);
    cudaGetSymbolAddress(&p_attn, g_attn);
    cudaGetSymbolAddress(&p_x1,   g_x1);
    cudaGetSymbolAddress(&p_h2,   g_h2);
    cudaGetSymbolAddress(&p_hid,  g_hid);
    cudaGetSymbolAddress(&p_wq,   g_wq);
    cudaGetSymbolAddress(&p_wp,   g_wp);
    cudaGetSymbolAddress(&p_w1,   g_w1);
    cudaGetSymbolAddress(&p_w2,   g_w2);

    // weights -> bf16
    cvt_kernel<<<768, 256>>>(qkvw,  (__nv_bfloat16*)p_wq, 768 * 256);
    cvt_kernel<<<256, 256>>>(projw, (__nv_bfloat16*)p_wp, 256 * 256);
    cvt_kernel<<<1024, 256>>>(fc1w, (__nv_bfloat16*)p_w1, 1024 * 256);
    cvt_kernel<<<1024, 256>>>(fc2w, (__nv_bfloat16*)p_w2, 256 * 1024);

    // LN1 + shift + window partition
    ln_kernel<true><<<ROWS_TOT / 8, 256>>>(x, n1w, n1b, (__nv_bfloat16*)p_hwin);
    // QKV GEMM
    gemm_kernel<0><<<dim3(1568, 6), 256>>>((const __nv_bfloat16*)p_hwin,
        (const __nv_bfloat16*)p_wq, qkvb, p_qkv, nullptr, ROWS_TOT, 768, 256);
    // Windowed attention
    attn_kernel<<<dim3(4096, 8), 128>>>((const __nv_bfloat16*)p_qkv, rpb,
                                        (__nv_bfloat16*)p_attn);
    // proj GEMM + window reverse + unshift + residual -> x1 (fp32)
    gemm_kernel<1><<<dim3(1568, 2), 256>>>((const __nv_bfloat16*)p_attn,
        (const __nv_bfloat16*)p_wp, projb, p_x1, x, ROWS_TOT, 256, 256);
    // LN2
    ln_kernel<false><<<ROWS_TOT / 8, 256>>>((const float*)p_x1, n2w, n2b,
                                            (__nv_bfloat16*)p_h2);
    // FC1 + exact GELU
    gemm_kernel<2><<<dim3(1568, 8), 256>>>((const __nv_bfloat16*)p_h2,
        (const __nv_bfloat16*)p_w1, fc1b, p_hid, nullptr, ROWS_TOT, 1024, 256);
    // FC2 + residual -> d_out (fp32)
    gemm_kernel<3><<<dim3(1568, 2), 256>>>((const __nv_bfloat16*)p_hid,
        (const __nv_bfloat16*)p_w2, fc2b, d_out, (const float*)p_x1,
        ROWS_TOT, 256, 1024);
}

// round 3
// speedup vs baseline: 1.1571x; 1.1571x over previous
#include <cuda_runtime.h>
#include <cuda_bf16.h>

// ---------------------------------------------------------------------------
// Problem constants: B=64, H=W=56, C=256, NH=8, WS=7, SS=3, HID=1024, N=49
// ---------------------------------------------------------------------------
#define ROWS_TOT 200704

// ---------------------------------------------------------------------------
// Scratch (device globals — no allocation allowed)
// ---------------------------------------------------------------------------
__device__ __nv_bfloat16 g_hwin[(size_t)ROWS_TOT * 256];
__device__ __nv_bfloat16 g_qkv [(size_t)ROWS_TOT * 768];
__device__ __nv_bfloat16 g_attn[(size_t)ROWS_TOT * 256];
__device__ float         g_x1  [(size_t)ROWS_TOT * 256];
__device__ __nv_bfloat16 g_h2  [(size_t)ROWS_TOT * 256];
__device__ __nv_bfloat16 g_hid [(size_t)ROWS_TOT * 1024];
__device__ __nv_bfloat16 g_wq[768 * 256];
__device__ __nv_bfloat16 g_wp[256 * 256];
__device__ __nv_bfloat16 g_w1[1024 * 256];
__device__ __nv_bfloat16 g_w2[256 * 1024];

// ---------------------------------------------------------------------------
// windowed row -> x row (roll -3 + window partition; also the inverse map)
// ---------------------------------------------------------------------------
__device__ __forceinline__ int win2x(int m) {
    int b   = m / 3136;
    int r   = m - b * 3136;
    int w64 = r / 49;
    int tok = r - w64 * 49;
    int wi = w64 >> 3, wj = w64 & 7;
    int i = tok / 7, j = tok - (tok / 7) * 7;
    int hh = wi * 7 + i + 3; hh = (hh >= 56) ? hh - 56 : hh;
    int ww = wj * 7 + j + 3; ww = (ww >= 56) ? ww - 56 : ww;
    return b * 3136 + hh * 56 + ww;
}

// ---------------------------------------------------------------------------
// PTX helpers
// ---------------------------------------------------------------------------
__device__ __forceinline__ unsigned cvta_s(const void* p) {
    return (unsigned)__cvta_generic_to_shared(p);
}
__device__ __forceinline__ void cp16(void* s, const void* g) {
    asm volatile("cp.async.cg.shared.global [%0], [%1], 16;\n"
                 :: "r"(cvta_s(s)), "l"(g));
}
__device__ __forceinline__ void cp_commit() {
    asm volatile("cp.async.commit_group;\n");
}
template <int N> __device__ __forceinline__ void cp_wait() {
    asm volatile("cp.async.wait_group %0;\n" :: "n"(N));
}
__device__ __forceinline__ void ldsm4(unsigned& r0, unsigned& r1,
                                      unsigned& r2, unsigned& r3, const void* p) {
    asm volatile("ldmatrix.sync.aligned.m8n8.x4.shared.b16 {%0,%1,%2,%3}, [%4];\n"
                 : "=r"(r0), "=r"(r1), "=r"(r2), "=r"(r3) : "r"(cvta_s(p)));
}
__device__ __forceinline__ void mma_bf16(float c[4], const unsigned a[4], const unsigned b[2]) {
    asm volatile(
        "mma.sync.aligned.m16n8k16.row.col.f32.bf16.bf16.f32 "
        "{%0,%1,%2,%3}, {%4,%5,%6,%7}, {%8,%9}, {%0,%1,%2,%3};\n"
        : "+f"(c[0]), "+f"(c[1]), "+f"(c[2]), "+f"(c[3])
        : "r"(a[0]), "r"(a[1]), "r"(a[2]), "r"(a[3]), "r"(b[0]), "r"(b[1]));
}
__device__ __forceinline__ unsigned long long ffma2(
    unsigned long long a, unsigned long long b, unsigned long long c) {
    unsigned long long d;
    asm("fma.rn.f32x2 %0, %1, %2, %3;\n" : "=l"(d) : "l"(a), "l"(b), "l"(c));
    return d;
}
union F2U { float2 f; unsigned long long u; };

// ---------------------------------------------------------------------------
// fused fp32 -> bf16 weight conversion (all 4 weight tensors in one launch)
// ---------------------------------------------------------------------------
__global__ void cvt4_kernel(const float* __restrict__ s0, __nv_bfloat16* __restrict__ d0, int n0,
                            const float* __restrict__ s1, __nv_bfloat16* __restrict__ d1, int n1,
                            const float* __restrict__ s2, __nv_bfloat16* __restrict__ d2, int n2,
                            const float* __restrict__ s3, __nv_bfloat16* __restrict__ d3, int n3) {
    int i = blockIdx.x * blockDim.x + threadIdx.x;
    if (i < n0) { d0[i] = __float2bfloat16(s0[i]); return; }
    i -= n0;
    if (i < n1) { d1[i] = __float2bfloat16(s1[i]); return; }
    i -= n1;
    if (i < n2) { d2[i] = __float2bfloat16(s2[i]); return; }
    i -= n2;
    if (i < n3) { d3[i] = __float2bfloat16(s3[i]); }
}

// ---------------------------------------------------------------------------
// LayerNorm (one warp per 256-col row); REMAP = shift+window-partition gather
// ---------------------------------------------------------------------------
template <bool REMAP>
__global__ __launch_bounds__(256) void ln_kernel(
    const float* __restrict__ X, const float* __restrict__ gw,
    const float* __restrict__ gb, __nv_bfloat16* __restrict__ out)
{
    int row  = blockIdx.x * 8 + (threadIdx.x >> 5);
    int lane = threadIdx.x & 31;
    int src  = REMAP ? win2x(row) : row;
    const float4* xr = (const float4*)(X + (size_t)src * 256) + lane * 2;
    float4 u0 = xr[0], u1 = xr[1];
    float s  = u0.x + u0.y + u0.z + u0.w + u1.x + u1.y + u1.z + u1.w;
    float s2 = u0.x*u0.x + u0.y*u0.y + u0.z*u0.z + u0.w*u0.w
             + u1.x*u1.x + u1.y*u1.y + u1.z*u1.z + u1.w*u1.w;
#pragma unroll
    for (int o = 16; o > 0; o >>= 1) {
        s  += __shfl_xor_sync(0xffffffffu, s, o);
        s2 += __shfl_xor_sync(0xffffffffu, s2, o);
    }
    float mean = s * (1.f / 256.f);
    float var  = s2 * (1.f / 256.f) - mean * mean;
    float inv  = rsqrtf(var + 1e-5f);
    const float4* wr = (const float4*)gw + lane * 2;
    const float4* br = (const float4*)gb + lane * 2;
    float4 w0 = wr[0], w1 = wr[1], b0 = br[0], b1 = br[1];
    __nv_bfloat162 o2[4];
    o2[0].x = __float2bfloat16((u0.x - mean) * inv * w0.x + b0.x);
    o2[0].y = __float2bfloat16((u0.y - mean) * inv * w0.y + b0.y);
    o2[1].x = __float2bfloat16((u0.z - mean) * inv * w0.z + b0.z);
    o2[1].y = __float2bfloat16((u0.w - mean) * inv * w0.w + b0.w);
    o2[2].x = __float2bfloat16((u1.x - mean) * inv * w1.x + b1.x);
    o2[2].y = __float2bfloat16((u1.y - mean) * inv * w1.y + b1.y);
    o2[3].x = __float2bfloat16((u1.z - mean) * inv * w1.z + b1.z);
    o2[3].y = __float2bfloat16((u1.w - mean) * inv * w1.w + b1.w);
    *(uint4*)(out + (size_t)row * 256 + lane * 8) = *(uint4*)o2;
}

__device__ __forceinline__ float gelu_exact(float v) {
    return 0.5f * v * (1.f + erff(v * 0.70710678118654752f));
}

// ---------------------------------------------------------------------------
// bf16 mma GEMM, 128x128x32 tile, 256 thr, cp.async 3-stage, ldmatrix, swizzle.
// Epilogues: 0 bf16 (QKV); 1 fp32 Res[win2x(r)]+acc (proj); 2 gelu bf16 (FC1);
//            3 fp32 Res[r]+acc (FC2 -> d_out)
// Smem: 3 stages x (A,B) x 128x32 bf16 = 48KB static. XOR swizzle:
//   chunk' = chunk ^ ((row>>1)&3), chunk = 16B unit within a 64B row.
// ---------------------------------------------------------------------------
__device__ __forceinline__ int swz(int row, int chunk) {
    return row * 32 + ((chunk ^ ((row >> 1) & 3)) << 3);
}

template <int EPI>
__global__ __launch_bounds__(256) void gemm_kernel(
    const __nv_bfloat16* __restrict__ A, const __nv_bfloat16* __restrict__ Bw,
    const float* __restrict__ bias, void* __restrict__ Out,
    const float* __restrict__ Res, int M, int N, int K)
{
    __shared__ __nv_bfloat16 As[3][128 * 32];
    __shared__ __nv_bfloat16 Bs[3][128 * 32];
    const int tid  = threadIdx.x;
    const int n0   = blockIdx.x * 128, m0 = blockIdx.y * 128;
    const int lane = tid & 31, warp = tid >> 5;
    const int wm = (warp & 1) * 64, wn = (warp >> 1) * 32;
    const int gr = lane >> 2, kc = (lane & 3) * 2;
    const int vr = tid >> 2, vchunk = tid & 3;   // staging: row 0..63, chunk 0..3
    const int lr = lane & 15, lk = lane >> 4;    // ldmatrix addressing

    float acc[4][4][4];
#pragma unroll
    for (int a = 0; a < 4; a++)
#pragma unroll
        for (int b = 0; b < 4; b++)
#pragma unroll
            for (int c = 0; c < 4; c++) acc[a][b][c] = 0.f;

    const __nv_bfloat16* Ag = A  + (size_t)m0 * K;
    const __nv_bfloat16* Bg = Bw + (size_t)n0 * K;

#define ISSUE(ST, KO)                                                          \
    do {                                                                       \
        if ((KO) < K) {                                                        \
            const __nv_bfloat16* a_ = Ag + (size_t)vr * K + (KO) + vchunk * 8; \
            cp16(&As[ST][swz(vr, vchunk)],      a_);                           \
            cp16(&As[ST][swz(vr + 64, vchunk)], a_ + (size_t)64 * K);          \
            const __nv_bfloat16* b_ = Bg + (size_t)vr * K + (KO) + vchunk * 8; \
            cp16(&Bs[ST][swz(vr, vchunk)],      b_);                           \
            cp16(&Bs[ST][swz(vr + 64, vchunk)], b_ + (size_t)64 * K);          \
        }                                                                      \
        cp_commit();                                                           \
    } while (0)

    const int kt = K >> 5;
    ISSUE(0, 0);
    ISSUE(1, 32);

    for (int it = 0; it < kt; it++) {
        cp_wait<1>();
        __syncthreads();
        ISSUE((it + 2) % 3, (it + 2) << 5);
        const int st = it % 3;
#pragma unroll
        for (int kk = 0; kk < 32; kk += 16) {
            unsigned af[4][4], bfr[4][2];
            const int ch = (kk >> 3) + lk;
#pragma unroll
            for (int mt = 0; mt < 4; mt++)
                ldsm4(af[mt][0], af[mt][1], af[mt][2], af[mt][3],
                      &As[st][swz(wm + mt * 16 + lr, ch)]);
#pragma unroll
            for (int ntp = 0; ntp < 2; ntp++) {
                unsigned r0, r1, r2, r3;
                ldsm4(r0, r1, r2, r3, &Bs[st][swz(wn + ntp * 16 + lr, ch)]);
                bfr[2 * ntp][0] = r0; bfr[2 * ntp + 1][0] = r1;
                bfr[2 * ntp][1] = r2; bfr[2 * ntp + 1][1] = r3;
            }
#pragma unroll
            for (int mt = 0; mt < 4; mt++)
#pragma unroll
                for (int nt = 0; nt < 4; nt++)
                    mma_bf16(acc[mt][nt], af[mt], bfr[nt]);
        }
    }
#undef ISSUE

    // epilogue
#pragma unroll
    for (int mt = 0; mt < 4; mt++) {
#pragma unroll
        for (int hh = 0; hh < 2; hh++) {
            int r = m0 + wm + mt * 16 + gr + hh * 8;
            int orow = (EPI == 1) ? win2x(r) : r;
#pragma unroll
            for (int nt = 0; nt < 4; nt++) {
                int col = n0 + wn + nt * 8 + kc;
                float2 bb = *(const float2*)&bias[col];
                float v0 = acc[mt][nt][hh * 2 + 0] + bb.x;
                float v1 = acc[mt][nt][hh * 2 + 1] + bb.y;
                if (EPI == 0) {
                    __nv_bfloat162 o; o.x = __float2bfloat16(v0); o.y = __float2bfloat16(v1);
                    *(__nv_bfloat162*)((__nv_bfloat16*)Out + (size_t)r * N + col) = o;
                } else if (EPI == 2) {
                    __nv_bfloat162 o;
                    o.x = __float2bfloat16(gelu_exact(v0));
                    o.y = __float2bfloat16(gelu_exact(v1));
                    *(__nv_bfloat162*)((__nv_bfloat16*)Out + (size_t)r * N + col) = o;
                } else {
                    float2 rr = *(const float2*)&Res[(size_t)orow * N + col];
                    float2 o; o.x = rr.x + v0; o.y = rr.y + v1;
                    *(float2*)((float*)Out + (size_t)orow * N + col) = o;
                }
            }
        }
    }
}

// ---------------------------------------------------------------------------
// Attention: one CTA per (window, head). N=49, hd=32. Packed f32x2 FMA.
// ---------------------------------------------------------------------------
__global__ __launch_bounds__(128) void attn_kernel(
    const __nv_bfloat16* __restrict__ qkv, const float* __restrict__ rpb,
    __nv_bfloat16* __restrict__ outp)
{
    __shared__ float ks[49 * 32];
    __shared__ float vs[49 * 32];
    __shared__ float sm[49 * 50];
    __shared__ float bs[169];
    __shared__ int gids[49];
    const int win = blockIdx.x, head = blockIdx.y;
    const int tid = threadIdx.x;
    const size_t qkvbase = (size_t)win * 49 * 768 + head * 32;

    for (int idx = tid; idx < 49 * 16; idx += 128) {
        int n = idx >> 4, d2 = (idx & 15) * 2;
        const __nv_bfloat16* p = qkv + qkvbase + (size_t)n * 768 + d2;
        __nv_bfloat162 k2 = *(const __nv_bfloat162*)(p + 256);
        __nv_bfloat162 v2 = *(const __nv_bfloat162*)(p + 512);
        ks[n * 32 + d2]     = __bfloat162float(k2.x);
        ks[n * 32 + d2 + 1] = __bfloat162float(k2.y);
        vs[n * 32 + d2]     = __bfloat162float(v2.x);
        vs[n * 32 + d2 + 1] = __bfloat162float(v2.y);
    }
    for (int i = tid; i < 169; i += 128) bs[i] = rpb[i * 8 + head];
    if (tid < 49) {
        int w64 = win & 63;
        int hh = (w64 >> 3) * 7 + tid / 7;
        int ww = (w64 & 7) * 7 + tid % 7;
        int gh = hh < 49 ? 0 : (hh < 53 ? 1 : 2);
        int gw = ww < 49 ? 0 : (ww < 53 ? 1 : 2);
        gids[tid] = gh * 3 + gw;
    }
    __syncthreads();

    const int n = tid >> 1, half = tid & 1;
    if (n < 49) {
        unsigned long long q2[16];
        const __nv_bfloat16* qp = qkv + qkvbase + (size_t)n * 768;
#pragma unroll
        for (int d2 = 0; d2 < 16; d2++) {
            __nv_bfloat162 qq = *(const __nv_bfloat162*)(qp + d2 * 2);
            F2U u;
            u.f.x = __bfloat162float(qq.x) * 0.17677669529663687f;
            u.f.y = __bfloat162float(qq.y) * 0.17677669529663687f;
            q2[d2] = u.u;
        }
        int gn = gids[n];
        int in_ = n / 7, jn = n - in_ * 7;
        for (int mi = 0; mi < 25; mi++) {
            int m = mi * 2 + half;
            if (m > 48) break;
            unsigned long long acc = 0ull;
            const unsigned long long* krow = (const unsigned long long*)(ks + m * 32);
#pragma unroll
            for (int d2 = 0; d2 < 16; d2++) acc = ffma2(q2[d2], krow[d2], acc);
            F2U u; u.u = acc;
            int im = m / 7, jm = m - im * 7;
            float bv  = bs[(in_ - im + 6) * 13 + (jn - jm + 6)];
            float msk = (gids[m] != gn) ? -100.f : 0.f;
            sm[n * 50 + m] = u.f.x + u.f.y + bv + msk;
        }
    }
    __syncwarp();
    float mx = -1e30f;
    if (n < 49)
        for (int m = half; m < 49; m += 2) mx = fmaxf(mx, sm[n * 50 + m]);
    mx = fmaxf(mx, __shfl_xor_sync(0xffffffffu, mx, 1));
    float ssum = 0.f;
    if (n < 49)
        for (int m = half; m < 49; m += 2) {
            float e = __expf(sm[n * 50 + m] - mx);
            sm[n * 50 + m] = e;
            ssum += e;
        }
    ssum += __shfl_xor_sync(0xffffffffu, ssum, 1);
    __syncthreads();

    if (n < 49) {
        float invs = 1.f / ssum;
        const int d0 = half * 16;
        unsigned long long acc2[8];
#pragma unroll
        for (int j = 0; j < 8; j++) acc2[j] = 0ull;
        for (int m = 0; m < 49; m++) {
            float s = sm[n * 50 + m];
            F2U s2; s2.f.x = s; s2.f.y = s;
            const unsigned long long* vrow = (const unsigned long long*)(vs + m * 32 + d0);
#pragma unroll
            for (int j = 0; j < 8; j++) acc2[j] = ffma2(s2.u, vrow[j], acc2[j]);
        }
        size_t ob = (size_t)(win * 49 + n) * 256 + head * 32 + d0;
        __nv_bfloat162 o2[8];
#pragma unroll
        for (int j = 0; j < 8; j++) {
            F2U u; u.u = acc2[j];
            o2[j].x = __float2bfloat16(u.f.x * invs);
            o2[j].y = __float2bfloat16(u.f.y * invs);
        }
        *(uint4*)(outp + ob)     = *(uint4*)&o2[0];
        *(uint4*)(outp + ob + 8) = *(uint4*)&o2[4];
    }
}

// ---------------------------------------------------------------------------
// Launch
// ---------------------------------------------------------------------------
extern "C" void kernel_launch(void* const* d_in, const int* in_sizes, int n_in,
                              void* d_out, int out_size)
{
    const float* x     = (const float*)d_in[0];
    const float* n1w   = (const float*)d_in[1];
    const float* n1b   = (const float*)d_in[2];
    const float* qkvw  = (const float*)d_in[3];
    const float* qkvb  = (const float*)d_in[4];
    const float* rpb   = (const float*)d_in[5];
    const float* projw = (const float*)d_in[6];
    const float* projb = (const float*)d_in[7];
    const float* n2w   = (const float*)d_in[8];
    const float* n2b   = (const float*)d_in[9];
    const float* fc1w  = (const float*)d_in[10];
    const float* fc1b  = (const float*)d_in[11];
    const float* fc2w  = (const float*)d_in[12];
    const float* fc2b  = (const float*)d_in[13];

    void *p_hwin, *p_qkv, *p_attn, *p_x1, *p_h2, *p_hid, *p_wq, *p_wp, *p_w1, *p_w2;
    cudaGetSymbolAddress(&p_hwin, g_hwin);
    cudaGetSymbolAddress(&p_qkv,  g_qkv);
    cudaGetSymbolAddress(&p_attn, g_attn);
    cudaGetSymbolAddress(&p_x1,   g_x1);
    cudaGetSymbolAddress(&p_h2,   g_h2);
    cudaGetSymbolAddress(&p_hid,  g_hid);
    cudaGetSymbolAddress(&p_wq,   g_wq);
    cudaGetSymbolAddress(&p_wp,   g_wp);
    cudaGetSymbolAddress(&p_w1,   g_w1);
    cudaGetSymbolAddress(&p_w2,   g_w2);

    // all weights -> bf16 in one launch
    cvt4_kernel<<<3072, 256>>>(qkvw, (__nv_bfloat16*)p_wq, 768 * 256,
                               projw, (__nv_bfloat16*)p_wp, 256 * 256,
                               fc1w, (__nv_bfloat16*)p_w1, 1024 * 256,
                               fc2w, (__nv_bfloat16*)p_w2, 256 * 1024);

    // LN1 + shift + window partition
    ln_kernel<true><<<ROWS_TOT / 8, 256>>>(x, n1w, n1b, (__nv_bfloat16*)p_hwin);
    // QKV GEMM (col-tiles on x for L2 reuse of A)
    gemm_kernel<0><<<dim3(6, 1568), 256>>>((const __nv_bfloat16*)p_hwin,
        (const __nv_bfloat16*)p_wq, qkvb, p_qkv, nullptr, ROWS_TOT, 768, 256);
    // Windowed attention
    attn_kernel<<<dim3(4096, 8), 128>>>((const __nv_bfloat16*)p_qkv, rpb,
                                        (__nv_bfloat16*)p_attn);
    // proj GEMM + window reverse + unshift + residual -> x1 (fp32)
    gemm_kernel<1><<<dim3(2, 1568), 256>>>((const __nv_bfloat16*)p_attn,
        (const __nv_bfloat16*)p_wp, projb, p_x1, x, ROWS_TOT, 256, 256);
    // LN2
    ln_kernel<false><<<ROWS_TOT / 8, 256>>>((const float*)p_x1, n2w, n2b,
                                            (__nv_bfloat16*)p_h2);
    // FC1 + exact GELU
    gemm_kernel<2><<<dim3(8, 1568), 256>>>((const __nv_bfloat16*)p_h2,
        (const __nv_bfloat16*)p_w1, fc1b, p_hid, nullptr, ROWS_TOT, 1024, 256);
    // FC2 + residual -> d_out (fp32)
    gemm_kernel<3><<<dim3(2, 1568), 256>>>((const __nv_bfloat16*)p_hid,
        (const __nv_bfloat16*)p_w2, fc2b, d_out, (const float*)p_x1,
        ROWS_TOT, 256, 1024);
}